// round 12
// baseline (speedup 1.0000x reference)
#include <cuda_runtime.h>
#include <cuda_fp16.h>
#include <cstdint>

#define B_  32
#define N_  2048
#define K_  128
#define CI_ 16
#define CO_ 16
#define KD_ (K_*CO_)   // 2048

typedef unsigned long long ull;

// XOR swizzle: permutes 16B cells within 1KB atoms -> conflict-free
#define SW(o) ((o) ^ (((o) >> 3) & 0x70))

// cp.async helpers
#define CP_ASYNC16(saddr, gptr) \
    asm volatile("cp.async.cg.shared.global [%0], [%1], 16;" :: "r"(saddr), "l"(gptr))
#define CP_COMMIT() asm volatile("cp.async.commit_group;")
#define CP_WAIT0()  asm volatile("cp.async.wait_group 0;" ::: "memory")
#define CP_WAIT1()  asm volatile("cp.async.wait_group 1;" ::: "memory")
#define CP_WAIT2()  asm volatile("cp.async.wait_group 2;" ::: "memory")

// ---------------- scratch (device globals; no allocation allowed) ----------------
__device__ __half g_uhat[(size_t)B_ * N_ * KD_];   // [b][i][k][d]  fp16, 268MB
__device__ float  g_t[3][B_ * KD_];
__device__ float  g_S[2][B_ * K_];
__device__ float  g_v[2][B_ * KD_];
__device__ float  g_vn[2][B_ * K_];

// ---------------- f32x2 packed helpers ----------------
__device__ __forceinline__ ull pack2(float a, float b) {
    ull r; asm("mov.b64 %0, {%1,%2};" : "=l"(r) : "f"(a), "f"(b)); return r;
}
__device__ __forceinline__ void unpack2(ull v, float& a, float& b) {
    asm("mov.b64 {%0,%1}, %2;" : "=f"(a), "=f"(b) : "l"(v));
}
__device__ __forceinline__ void ffma2(ull& d, ull a, ull b) {
    asm("fma.rn.f32x2 %0, %1, %2, %0;" : "+l"(d) : "l"(a), "l"(b));
}
__device__ __forceinline__ void fadd2(ull& d, ull a) {
    asm("add.rn.f32x2 %0, %0, %1;" : "+l"(d) : "l"(a));
}

// labels dtype-agnostic (int32 vs int64); labels = arange(128)
__device__ __forceinline__ int load_label(const void* labels, int k) {
    const int* p32 = (const int*)labels;
    if (p32[1] == 1) return p32[k];
    return (int)((const long long*)labels)[k];
}

// ---------------- init ----------------
__global__ void k_init() {
    int idx = blockIdx.x * 256 + threadIdx.x;
    if (idx < 3 * B_ * KD_) (&g_t[0][0])[idx] = 0.f;
    if (idx < 2 * B_ * K_)  (&g_S[0][0])[idx] = 0.f;
}

// ---------------- pass 1: cp.async-staged W (depth-3, barrier-free) ------------
// Each thread's 64B W-row per ii is staged into its private pitch-80 SMEM slot.
// No __syncthreads in the mainloop: threads read only their own copies, ordered
// by cp.async.wait_group + program order (pack2 consumes LDS before refill issue).
__global__ void __launch_bounds__(256, 2) k_pass1(const float* __restrict__ x,
                                                  const void* __restrict__ labels,
                                                  const float* __restrict__ W1) {
    extern __shared__ __align__(16) char ps[];
    float* xs = (float*)ps;                 // 32KB: [i][(bp*16+c)*2 + (b&1)]
    char*  wb = ps + 32768;                 // 3 x 20480 (pitch-80 per-thread slots)
    const uint32_t wb_s = (uint32_t)__cvta_generic_to_shared(wb);

    const int tid = threadIdx.x;
    const int kd  = blockIdx.y * 256 + tid;        // 0..2047
    const int k   = kd >> 4;
    const int d   = kd & 15;
    int ksrc = load_label(labels, k);
    if ((unsigned)ksrc >= (unsigned)K_) ksrc = k;
    const int i0  = blockIdx.x * 16;

    const char*  wrow  = (const char*)(W1 + (((size_t)i0 * K_ + ksrc) * CO_ + d) * CI_);
    const size_t wstep = (size_t)K_ * CO_ * CI_ * 4;   // 128KB per i

    // prime the W pipeline: ii = 0,1,2
#pragma unroll
    for (int p = 0; p < 3; p++) {
        uint32_t dst = wb_s + p * 20480 + tid * 80;
        const char* s = wrow + (size_t)p * wstep;
        CP_ASYNC16(dst,      s);
        CP_ASYNC16(dst + 16, s + 16);
        CP_ASYNC16(dst + 32, s + 32);
        CP_ASYNC16(dst + 48, s + 48);
        CP_COMMIT();
    }

    // stage x[:, i0:i0+16, :] pair-packed (overlaps the W transfers)
    for (int e = tid; e < 8192; e += 256) {
        const int b = e >> 8, rem = e & 255, i = rem >> 4, c = rem & 15;
        xs[i * 512 + ((b >> 1) * 16 + c) * 2 + (b & 1)] =
            x[((size_t)b * N_ + i0 + i) * CI_ + c];
    }
    __syncthreads();

    ull tsum[16];
#pragma unroll
    for (int bp = 0; bp < 16; bp++) tsum[bp] = 0ull;

    for (int ii = 0; ii < 16; ii++) {
        if (ii < 14) { CP_WAIT2(); } else if (ii == 14) { CP_WAIT1(); } else { CP_WAIT0(); }

        const float4* wt = (const float4*)(wb + (ii % 3) * 20480 + tid * 80);
        float4 cw0 = wt[0], cw1 = wt[1], cw2 = wt[2], cw3 = wt[3];
        ull wd[16];
        wd[0]=pack2(cw0.x,cw0.x); wd[1]=pack2(cw0.y,cw0.y); wd[2]=pack2(cw0.z,cw0.z); wd[3]=pack2(cw0.w,cw0.w);
        wd[4]=pack2(cw1.x,cw1.x); wd[5]=pack2(cw1.y,cw1.y); wd[6]=pack2(cw1.z,cw1.z); wd[7]=pack2(cw1.w,cw1.w);
        wd[8]=pack2(cw2.x,cw2.x); wd[9]=pack2(cw2.y,cw2.y); wd[10]=pack2(cw2.z,cw2.z); wd[11]=pack2(cw2.w,cw2.w);
        wd[12]=pack2(cw3.x,cw3.x); wd[13]=pack2(cw3.y,cw3.y); wd[14]=pack2(cw3.z,cw3.z); wd[15]=pack2(cw3.w,cw3.w);

        // refill this ring slot for ii+3 (safe: pack2 already consumed the LDS data)
        if (ii < 13) {
            uint32_t dst = wb_s + (ii % 3) * 20480 + tid * 80;
            const char* s = wrow + (size_t)(ii + 3) * wstep;
            CP_ASYNC16(dst,      s);
            CP_ASYNC16(dst + 16, s + 16);
            CP_ASYNC16(dst + 32, s + 32);
            CP_ASYNC16(dst + 48, s + 48);
            CP_COMMIT();
        }

        const int i = i0 + ii;
        __half* ubase = g_uhat + (size_t)i * KD_ + kd;
#pragma unroll
        for (int bp = 0; bp < 16; bp++) {
            const ulonglong2* xq = reinterpret_cast<const ulonglong2*>(xs + ii * 512 + bp * 32);
            ulonglong2 p0 = xq[0], p1 = xq[1], p2 = xq[2], p3 = xq[3];
            ulonglong2 p4 = xq[4], p5 = xq[5], p6 = xq[6], p7 = xq[7];
            ull acc0 = 0ull, acc1 = 0ull;
            ffma2(acc0, wd[0],  p0.x); ffma2(acc1, wd[1],  p0.y);
            ffma2(acc0, wd[2],  p1.x); ffma2(acc1, wd[3],  p1.y);
            ffma2(acc0, wd[4],  p2.x); ffma2(acc1, wd[5],  p2.y);
            ffma2(acc0, wd[6],  p3.x); ffma2(acc1, wd[7],  p3.y);
            ffma2(acc0, wd[8],  p4.x); ffma2(acc1, wd[9],  p4.y);
            ffma2(acc0, wd[10], p5.x); ffma2(acc1, wd[11], p5.y);
            ffma2(acc0, wd[12], p6.x); ffma2(acc1, wd[13], p6.y);
            ffma2(acc0, wd[14], p7.x); ffma2(acc1, wd[15], p7.y);
            fadd2(acc0, acc1);
            fadd2(tsum[bp], acc0);
            float lo, hi; unpack2(acc0, lo, hi);
            ubase[(size_t)(2 * bp)     * N_ * KD_] = __float2half_rn(lo);
            ubase[(size_t)(2 * bp + 1) * N_ * KD_] = __float2half_rn(hi);
        }
    }
#pragma unroll
    for (int bp = 0; bp < 16; bp++) {
        float a, bb; unpack2(tsum[bp], a, bb);
        atomicAdd(&g_t[0][(2 * bp)     * KD_ + kd], a);
        atomicAdd(&g_t[0][(2 * bp + 1) * KD_ + kd], bb);
    }
}

// ---------------- finalize ----------------
__global__ void k_finalize(int which) {
    const int idx = blockIdx.x * 256 + threadIdx.x;
    const float* t = g_t[which];
    float inv = (which == 0) ? (1.0f / 2048.0f) : (1.0f / g_S[0][idx]);
    const float4* tp = reinterpret_cast<const float4*>(t + idx * 16);
    float w[16]; float s2 = 0.f;
#pragma unroll
    for (int q = 0; q < 4; q++) {
        float4 tv = tp[q];
        w[q*4+0]=tv.x*inv; w[q*4+1]=tv.y*inv; w[q*4+2]=tv.z*inv; w[q*4+3]=tv.w*inv;
        s2 += w[q*4+0]*w[q*4+0] + w[q*4+1]*w[q*4+1] + w[q*4+2]*w[q*4+2] + w[q*4+3]*w[q*4+3];
    }
    float sc = sqrtf(s2) / (0.5f + s2);
    float4* vp = reinterpret_cast<float4*>(g_v[which] + idx * 16);
#pragma unroll
    for (int q = 0; q < 4; q++) {
        float4 o; o.x=sc*w[q*4+0]; o.y=sc*w[q*4+1]; o.z=sc*w[q*4+2]; o.w=sc*w[q*4+3];
        vp[q] = o;
    }
    g_vn[which][idx] = sc * sc * s2;
}

// ---------------- routing pass (R10 structure, unchanged) -----------------------
template <int IT>
__global__ void __launch_bounds__(128, 4) k_route() {
    extern __shared__ __align__(1024) char base[];
    float*  vn1  = (float*)base;                              // 512B
    float*  vn2  = (float*)(base + 512);                      // IT3
    char*   v1h  = base + ((IT == 3) ? 1024 : 512);           // 4KB half2 v0 (swizzled)
    char*   v2h  = base + 5120;                               // IT3: 4KB
    __half* cke  = (__half*)(base + ((IT == 3) ? 9216 : 4608)); // 1KB: [4 i][128 k]
    char*   bufs = base + ((IT == 3) ? 10240 : 6144);         // 3 x 16KB

    const int tid = threadIdx.x, lane = tid & 31, warp = tid >> 5;
    const int b   = blockIdx.x >> 6;
    const int ch  = blockIdx.x & 63;
    const int i0  = ch * 32;

    const uint32_t bufs_s = (uint32_t)__cvta_generic_to_shared(bufs);

#pragma unroll
    for (int q = 0; q < 3; q++) {
        const char* src = (const char*)(g_uhat + ((size_t)b * N_ + i0 + q * 4 + warp) * KD_);
        uint32_t dst = bufs_s + q * 16384 + warp * 4096;
#pragma unroll
        for (int c = 0; c < 8; c++) {
            int off = (c * 32 + lane) * 16;
            CP_ASYNC16(dst + SW(off), src + off);
        }
        CP_COMMIT();
    }

    for (int e = tid; e < 1024; e += 128) {
        float2 f = *(const float2*)(g_v[0] + b * KD_ + 2 * e);
        *(__half2*)(v1h + SW(e * 4)) = __float22half2_rn(f);
        if (IT == 3) {
            float2 g2 = *(const float2*)(g_v[1] + b * KD_ + 2 * e);
            *(__half2*)(v2h + SW(e * 4)) = __float22half2_rn(g2);
        }
    }
    vn1[tid] = g_vn[0][b * K_ + tid];
    if (IT == 3) vn2[tid] = g_vn[1][b * K_ + tid];

    float tacc[16];
#pragma unroll
    for (int m = 0; m < 16; m++) tacc[m] = 0.f;
    float sacc = 0.f;

#pragma unroll
    for (int q = 0; q < 8; q++) {
        if (q < 6) { CP_WAIT2(); } else if (q == 6) { CP_WAIT1(); } else { CP_WAIT0(); }
        __syncthreads();

        const char* mbuf = bufs + (q % 3) * 16384;
        const char* msl  = mbuf + warp * 4096;

        float lg[4];
#pragma unroll
        for (int j = 0; j < 4; j++) {
            const int k = lane + 32 * j;
            uint4 r0 = *(const uint4*)(msl + SW(k * 32));
            uint4 r1 = *(const uint4*)(msl + SW(k * 32 + 16));
            uint4 w0 = *(const uint4*)(v1h + SW(k * 32));
            uint4 w1 = *(const uint4*)(v1h + SW(k * 32 + 16));
            const __half2* u0 = (const __half2*)&r0;
            const __half2* u1 = (const __half2*)&r1;
            const __half2* a0 = (const __half2*)&w0;
            const __half2* a1 = (const __half2*)&w1;
            __half2 s2a = __hmul2(u0[0], u0[0]);
            __half2 s2b = __hmul2(u0[1], u0[1]);
            __half2 d1a = __hmul2(u0[0], a0[0]);
            __half2 d1b = __hmul2(u0[1], a0[1]);
            s2a = __hfma2(u0[2], u0[2], s2a);  d1a = __hfma2(u0[2], a0[2], d1a);
            s2b = __hfma2(u0[3], u0[3], s2b);  d1b = __hfma2(u0[3], a0[3], d1b);
            s2a = __hfma2(u1[0], u1[0], s2a);  d1a = __hfma2(u1[0], a1[0], d1a);
            s2b = __hfma2(u1[1], u1[1], s2b);  d1b = __hfma2(u1[1], a1[1], d1b);
            s2a = __hfma2(u1[2], u1[2], s2a);  d1a = __hfma2(u1[2], a1[2], d1a);
            s2b = __hfma2(u1[3], u1[3], s2b);  d1b = __hfma2(u1[3], a1[3], d1b);
            __half2 s2h = __hadd2(s2a, s2b);
            __half2 d1h = __hadd2(d1a, d1b);
            float dot2 = 0.f;
            if (IT == 3) {
                uint4 y0 = *(const uint4*)(v2h + SW(k * 32));
                uint4 y1 = *(const uint4*)(v2h + SW(k * 32 + 16));
                const __half2* b0 = (const __half2*)&y0;
                const __half2* b1 = (const __half2*)&y1;
                __half2 d2a = __hmul2(u0[0], b0[0]);
                __half2 d2b = __hmul2(u0[1], b0[1]);
                d2a = __hfma2(u0[2], b0[2], d2a);
                d2b = __hfma2(u0[3], b0[3], d2b);
                d2a = __hfma2(u1[0], b1[0], d2a);
                d2b = __hfma2(u1[1], b1[1], d2b);
                d2a = __hfma2(u1[2], b1[2], d2a);
                d2b = __hfma2(u1[3], b1[3], d2b);
                __half2 d2h = __hadd2(d2a, d2b);
                dot2 = __low2float(d2h) + __high2float(d2h);
            }
            float s2   = __low2float(s2h) + __high2float(s2h);
            float dot1 = __low2float(d1h) + __high2float(d1h);
            float sc = sqrtf(s2) / (0.5f + s2);
            float usq = sc * sc * s2;
            float dd = 1.f - (usq - 2.f * sc * dot1 + vn1[k]);
            if (IT == 3) dd += 1.f - (usq - 2.f * sc * dot2 + vn2[k]);
            lg[j] = dd;
        }
        float e0 = __expf(lg[0]), e1 = __expf(lg[1]), e2 = __expf(lg[2]), e3 = __expf(lg[3]);
        float ssum = (e0 + e1) + (e2 + e3);
#pragma unroll
        for (int o = 16; o > 0; o >>= 1) ssum += __shfl_xor_sync(0xffffffffu, ssum, o);
        const float invs = 1.f / ssum;
        cke[warp * 128 + lane +  0] = __float2half_rn(e0 * invs);
        cke[warp * 128 + lane + 32] = __float2half_rn(e1 * invs);
        cke[warp * 128 + lane + 64] = __float2half_rn(e2 * invs);
        cke[warp * 128 + lane + 96] = __float2half_rn(e3 * invs);

        __syncthreads();

        __half2 hq[8];
#pragma unroll
        for (int m = 0; m < 8; m++) hq[m] = __float2half2_rn(0.f);
        float sq = 0.f;
#pragma unroll
        for (int i8 = 0; i8 < 4; i8++) {
            __half c = cke[i8 * 128 + tid];
            __half2 c2 = __half2half2(c);
            uint4 a0 = *(const uint4*)(mbuf + i8 * 4096 + SW(tid * 32));
            uint4 a1 = *(const uint4*)(mbuf + i8 * 4096 + SW(tid * 32 + 16));
            const __half2* u0 = (const __half2*)&a0;
            const __half2* u1 = (const __half2*)&a1;
            hq[0] = __hfma2(u0[0], c2, hq[0]);
            hq[1] = __hfma2(u0[1], c2, hq[1]);
            hq[2] = __hfma2(u0[2], c2, hq[2]);
            hq[3] = __hfma2(u0[3], c2, hq[3]);
            hq[4] = __hfma2(u1[0], c2, hq[4]);
            hq[5] = __hfma2(u1[1], c2, hq[5]);
            hq[6] = __hfma2(u1[2], c2, hq[6]);
            hq[7] = __hfma2(u1[3], c2, hq[7]);
            sq += __half2float(c);
        }
#pragma unroll
        for (int m = 0; m < 8; m++) {
            float2 f = __half22float2(hq[m]);
            tacc[2*m]   += f.x;
            tacc[2*m+1] += f.y;
        }
        sacc += sq;

        __syncthreads();

        if (q < 5) {
            const char* src = (const char*)(g_uhat + ((size_t)b * N_ + i0 + (q + 3) * 4 + warp) * KD_);
            uint32_t dst = bufs_s + (q % 3) * 16384 + warp * 4096;
#pragma unroll
            for (int c = 0; c < 8; c++) {
                int off = (c * 32 + lane) * 16;
                CP_ASYNC16(dst + SW(off), src + off);
            }
            CP_COMMIT();
        }
    }

    float* gt = g_t[IT - 1] + b * KD_ + tid * 16;
#pragma unroll
    for (int m = 0; m < 16; m++) atomicAdd(gt + m, tacc[m]);
    atomicAdd(&g_S[IT - 2][b * K_ + tid], sacc);
}

// ---------------- final ----------------
__global__ void k_final(float* __restrict__ out) {
    const int idx = blockIdx.x * 256 + threadIdx.x;
    const float inv = 1.0f / g_S[1][idx];
    const float4* tp = reinterpret_cast<const float4*>(&g_t[2][0] + idx * 16);
    float w[16]; float s2 = 0.f;
#pragma unroll
    for (int q = 0; q < 4; q++) {
        float4 tv = tp[q];
        w[q*4+0]=tv.x*inv; w[q*4+1]=tv.y*inv; w[q*4+2]=tv.z*inv; w[q*4+3]=tv.w*inv;
        s2 += w[q*4+0]*w[q*4+0] + w[q*4+1]*w[q*4+1] + w[q*4+2]*w[q*4+2] + w[q*4+3]*w[q*4+3];
    }
    float sc = sqrtf(s2) / (0.5f + s2);
    float4* op = reinterpret_cast<float4*>(out + idx * 16);
#pragma unroll
    for (int q = 0; q < 4; q++) {
        float4 o; o.x=sc*w[q*4+0]; o.y=sc*w[q*4+1]; o.z=sc*w[q*4+2]; o.w=sc*w[q*4+3];
        op[q] = o;
    }
    out[B_ * KD_ + idx] = s2 / (0.5f + s2);  // ||v||
}

// ---------------- launch ----------------
extern "C" void kernel_launch(void* const* d_in, const int* in_sizes, int n_in,
                              void* d_out, int out_size) {
    const float* x      = (const float*)d_in[0];
    const void*  labels = d_in[2];
    const float* W1     = (const float*)d_in[3];
    float*       out    = (float*)d_out;

    const int SMEMP = 32768 + 3 * 20480;   // 94208 (pass1)
    const int SMEM2 = 6144  + 3 * 16384;   // 55296
    const int SMEM3 = 10240 + 3 * 16384;   // 59392
    cudaFuncSetAttribute((const void*)k_pass1,    cudaFuncAttributeMaxDynamicSharedMemorySize, SMEMP);
    cudaFuncSetAttribute((const void*)k_route<2>, cudaFuncAttributeMaxDynamicSharedMemorySize, SMEM2);
    cudaFuncSetAttribute((const void*)k_route<3>, cudaFuncAttributeMaxDynamicSharedMemorySize, SMEM3);

    k_init<<<768, 256>>>();
    k_pass1<<<dim3(128, 8), 256, SMEMP>>>(x, labels, W1);
    k_finalize<<<16, 256>>>(0);               // v0 = squash(sum_i u / 2048)
    k_route<2><<<2048, 128, SMEM2>>>();       // dd(v0) -> t1, S0
    k_finalize<<<16, 256>>>(1);               // v1 = squash(t1/S0)
    k_route<3><<<2048, 128, SMEM3>>>();       // dd(v0)+dd(v1) -> t2, S1
    k_final<<<16, 256>>>(out);                // poses + activations
    (void)in_sizes; (void)n_in; (void)out_size;
}

// round 13
// speedup vs baseline: 1.0518x; 1.0518x over previous
#include <cuda_runtime.h>
#include <cuda_fp16.h>
#include <cstdint>

#define B_  32
#define N_  2048
#define K_  128
#define CI_ 16
#define CO_ 16
#define KD_ (K_*CO_)   // 2048

typedef unsigned long long ull;

// XOR swizzle (used by pass1 x staging only now)
#define SW(o) ((o) ^ (((o) >> 3) & 0x70))

// cp.async helpers (pass1 W pipeline)
#define CP_ASYNC16(saddr, gptr) \
    asm volatile("cp.async.cg.shared.global [%0], [%1], 16;" :: "r"(saddr), "l"(gptr))
#define CP_COMMIT() asm volatile("cp.async.commit_group;")
#define CP_WAIT0()  asm volatile("cp.async.wait_group 0;" ::: "memory")
#define CP_WAIT1()  asm volatile("cp.async.wait_group 1;" ::: "memory")
#define CP_WAIT2()  asm volatile("cp.async.wait_group 2;" ::: "memory")

// ---------------- scratch (device globals; no allocation allowed) ----------------
__device__ __half g_uhat[(size_t)B_ * N_ * KD_];   // [b][i][k][d]  fp16, 268MB
__device__ float  g_t[3][B_ * KD_];
__device__ float  g_S[2][B_ * K_];
__device__ float  g_v[2][B_ * KD_];
__device__ float  g_vn[2][B_ * K_];

// ---------------- f32x2 packed helpers ----------------
__device__ __forceinline__ ull pack2(float a, float b) {
    ull r; asm("mov.b64 %0, {%1,%2};" : "=l"(r) : "f"(a), "f"(b)); return r;
}
__device__ __forceinline__ void unpack2(ull v, float& a, float& b) {
    asm("mov.b64 {%0,%1}, %2;" : "=f"(a), "=f"(b) : "l"(v));
}
__device__ __forceinline__ void ffma2(ull& d, ull a, ull b) {
    asm("fma.rn.f32x2 %0, %1, %2, %0;" : "+l"(d) : "l"(a), "l"(b));
}
__device__ __forceinline__ void fadd2(ull& d, ull a) {
    asm("add.rn.f32x2 %0, %0, %1;" : "+l"(d) : "l"(a));
}

// labels dtype-agnostic (int32 vs int64); labels = arange(128)
__device__ __forceinline__ int load_label(const void* labels, int k) {
    const int* p32 = (const int*)labels;
    if (p32[1] == 1) return p32[k];
    return (int)((const long long*)labels)[k];
}

// ---------------- init ----------------
__global__ void k_init() {
    int idx = blockIdx.x * 256 + threadIdx.x;
    if (idx < 3 * B_ * KD_) (&g_t[0][0])[idx] = 0.f;
    if (idx < 2 * B_ * K_)  (&g_S[0][0])[idx] = 0.f;
}

// ---------------- pass 1: cp.async-staged W (unchanged from R12) ----------------
__global__ void __launch_bounds__(256, 2) k_pass1(const float* __restrict__ x,
                                                  const void* __restrict__ labels,
                                                  const float* __restrict__ W1) {
    extern __shared__ __align__(16) char ps[];
    float* xs = (float*)ps;                 // 32KB
    char*  wb = ps + 32768;                 // 3 x 20480 (pitch-80 per-thread slots)
    const uint32_t wb_s = (uint32_t)__cvta_generic_to_shared(wb);

    const int tid = threadIdx.x;
    const int kd  = blockIdx.y * 256 + tid;
    const int k   = kd >> 4;
    const int d   = kd & 15;
    int ksrc = load_label(labels, k);
    if ((unsigned)ksrc >= (unsigned)K_) ksrc = k;
    const int i0  = blockIdx.x * 16;

    const char*  wrow  = (const char*)(W1 + (((size_t)i0 * K_ + ksrc) * CO_ + d) * CI_);
    const size_t wstep = (size_t)K_ * CO_ * CI_ * 4;

#pragma unroll
    for (int p = 0; p < 3; p++) {
        uint32_t dst = wb_s + p * 20480 + tid * 80;
        const char* s = wrow + (size_t)p * wstep;
        CP_ASYNC16(dst,      s);
        CP_ASYNC16(dst + 16, s + 16);
        CP_ASYNC16(dst + 32, s + 32);
        CP_ASYNC16(dst + 48, s + 48);
        CP_COMMIT();
    }

    for (int e = tid; e < 8192; e += 256) {
        const int b = e >> 8, rem = e & 255, i = rem >> 4, c = rem & 15;
        xs[i * 512 + ((b >> 1) * 16 + c) * 2 + (b & 1)] =
            x[((size_t)b * N_ + i0 + i) * CI_ + c];
    }
    __syncthreads();

    ull tsum[16];
#pragma unroll
    for (int bp = 0; bp < 16; bp++) tsum[bp] = 0ull;

    for (int ii = 0; ii < 16; ii++) {
        if (ii < 14) { CP_WAIT2(); } else if (ii == 14) { CP_WAIT1(); } else { CP_WAIT0(); }

        const float4* wt = (const float4*)(wb + (ii % 3) * 20480 + tid * 80);
        float4 cw0 = wt[0], cw1 = wt[1], cw2 = wt[2], cw3 = wt[3];
        ull wd[16];
        wd[0]=pack2(cw0.x,cw0.x); wd[1]=pack2(cw0.y,cw0.y); wd[2]=pack2(cw0.z,cw0.z); wd[3]=pack2(cw0.w,cw0.w);
        wd[4]=pack2(cw1.x,cw1.x); wd[5]=pack2(cw1.y,cw1.y); wd[6]=pack2(cw1.z,cw1.z); wd[7]=pack2(cw1.w,cw1.w);
        wd[8]=pack2(cw2.x,cw2.x); wd[9]=pack2(cw2.y,cw2.y); wd[10]=pack2(cw2.z,cw2.z); wd[11]=pack2(cw2.w,cw2.w);
        wd[12]=pack2(cw3.x,cw3.x); wd[13]=pack2(cw3.y,cw3.y); wd[14]=pack2(cw3.z,cw3.z); wd[15]=pack2(cw3.w,cw3.w);

        if (ii < 13) {
            uint32_t dst = wb_s + (ii % 3) * 20480 + tid * 80;
            const char* s = wrow + (size_t)(ii + 3) * wstep;
            CP_ASYNC16(dst,      s);
            CP_ASYNC16(dst + 16, s + 16);
            CP_ASYNC16(dst + 32, s + 32);
            CP_ASYNC16(dst + 48, s + 48);
            CP_COMMIT();
        }

        const int i = i0 + ii;
        __half* ubase = g_uhat + (size_t)i * KD_ + kd;
#pragma unroll
        for (int bp = 0; bp < 16; bp++) {
            const ulonglong2* xq = reinterpret_cast<const ulonglong2*>(xs + ii * 512 + bp * 32);
            ulonglong2 p0 = xq[0], p1 = xq[1], p2 = xq[2], p3 = xq[3];
            ulonglong2 p4 = xq[4], p5 = xq[5], p6 = xq[6], p7 = xq[7];
            ull acc0 = 0ull, acc1 = 0ull;
            ffma2(acc0, wd[0],  p0.x); ffma2(acc1, wd[1],  p0.y);
            ffma2(acc0, wd[2],  p1.x); ffma2(acc1, wd[3],  p1.y);
            ffma2(acc0, wd[4],  p2.x); ffma2(acc1, wd[5],  p2.y);
            ffma2(acc0, wd[6],  p3.x); ffma2(acc1, wd[7],  p3.y);
            ffma2(acc0, wd[8],  p4.x); ffma2(acc1, wd[9],  p4.y);
            ffma2(acc0, wd[10], p5.x); ffma2(acc1, wd[11], p5.y);
            ffma2(acc0, wd[12], p6.x); ffma2(acc1, wd[13], p6.y);
            ffma2(acc0, wd[14], p7.x); ffma2(acc1, wd[15], p7.y);
            fadd2(acc0, acc1);
            fadd2(tsum[bp], acc0);
            float lo, hi; unpack2(acc0, lo, hi);
            ubase[(size_t)(2 * bp)     * N_ * KD_] = __float2half_rn(lo);
            ubase[(size_t)(2 * bp + 1) * N_ * KD_] = __float2half_rn(hi);
        }
    }
#pragma unroll
    for (int bp = 0; bp < 16; bp++) {
        float a, bb; unpack2(tsum[bp], a, bb);
        atomicAdd(&g_t[0][(2 * bp)     * KD_ + kd], a);
        atomicAdd(&g_t[0][(2 * bp + 1) * KD_ + kd], bb);
    }
}

// ---------------- finalize ----------------
__global__ void k_finalize(int which) {
    const int idx = blockIdx.x * 256 + threadIdx.x;
    const float* t = g_t[which];
    float inv = (which == 0) ? (1.0f / 2048.0f) : (1.0f / g_S[0][idx]);
    const float4* tp = reinterpret_cast<const float4*>(t + idx * 16);
    float w[16]; float s2 = 0.f;
#pragma unroll
    for (int q = 0; q < 4; q++) {
        float4 tv = tp[q];
        w[q*4+0]=tv.x*inv; w[q*4+1]=tv.y*inv; w[q*4+2]=tv.z*inv; w[q*4+3]=tv.w*inv;
        s2 += w[q*4+0]*w[q*4+0] + w[q*4+1]*w[q*4+1] + w[q*4+2]*w[q*4+2] + w[q*4+3]*w[q*4+3];
    }
    float sc = sqrtf(s2) / (0.5f + s2);
    float4* vp = reinterpret_cast<float4*>(g_v[which] + idx * 16);
#pragma unroll
    for (int q = 0; q < 4; q++) {
        float4 o; o.x=sc*w[q*4+0]; o.y=sc*w[q*4+1]; o.z=sc*w[q*4+2]; o.w=sc*w[q*4+3];
        vp[q] = o;
    }
    g_vn[which][idx] = sc * sc * s2;
}

// ---------------- routing pass: register-resident u AND v, thread-owns-k --------
// grid 2048 (32 b * 64 chunks of 32 i); block 128. Thread tid owns k=tid for the
// whole kernel: v/vn in registers, u[i][tid] loaded by LDG (32B) and used from
// registers for BOTH logits and t-accumulation. Only softmax denominators cross
// threads (2KB SMEM block-reduce per 4-i group).
template <int IT>
__global__ void __launch_bounds__(128, 4) k_route() {
    __shared__ float e_sm[4][128];
    __shared__ float inv_sm[4];

    const int tid = threadIdx.x, lane = tid & 31, warp = tid >> 5;
    const int b   = blockIdx.x >> 6;
    const int ch  = blockIdx.x & 63;
    const int i0  = ch * 32;

    // register-resident v, vn for own k = tid
    __half2 v1r[8], v2r[8];
    {
        const float* vs = g_v[0] + b * KD_ + tid * 16;
#pragma unroll
        for (int m = 0; m < 8; m++) v1r[m] = __floats2half2_rn(vs[2*m], vs[2*m+1]);
        if (IT == 3) {
            const float* ws = g_v[1] + b * KD_ + tid * 16;
#pragma unroll
            for (int m = 0; m < 8; m++) v2r[m] = __floats2half2_rn(ws[2*m], ws[2*m+1]);
        }
    }
    const float vn1r = g_vn[0][b * K_ + tid];
    const float vn2r = (IT == 3) ? g_vn[1][b * K_ + tid] : 0.f;

    // u row base for own k; i stride = 4096 bytes
    const char* ubase = (const char*)(g_uhat + ((size_t)b * N_ + i0) * KD_) + tid * 32;

    // double-buffered register u: [parity][j][2]
    uint4 ub[2][4][2];
#pragma unroll
    for (int j = 0; j < 4; j++) {
        const char* p = ubase + (size_t)j * 4096;
        ub[0][j][0] = __ldg((const uint4*)p);
        ub[0][j][1] = __ldg((const uint4*)(p + 16));
    }

    float tacc[16];
#pragma unroll
    for (int m = 0; m < 16; m++) tacc[m] = 0.f;
    float sacc = 0.f;

#pragma unroll
    for (int q = 0; q < 8; q++) {
        // prefetch group q+1 into the other parity (8 independent LDG.128)
        if (q < 7) {
            const char* pn = ubase + (size_t)(q + 1) * 4 * 4096;
#pragma unroll
            for (int j = 0; j < 4; j++) {
                ub[(q + 1) & 1][j][0] = __ldg((const uint4*)(pn + (size_t)j * 4096));
                ub[(q + 1) & 1][j][1] = __ldg((const uint4*)(pn + (size_t)j * 4096 + 16));
            }
        }

        // logits + exp for own k, 4 i's (all from registers)
        float e[4];
#pragma unroll
        for (int j = 0; j < 4; j++) {
            const __half2* u0 = (const __half2*)&ub[q & 1][j][0];
            const __half2* u1 = (const __half2*)&ub[q & 1][j][1];
            __half2 s2a = __hmul2(u0[0], u0[0]);
            __half2 s2b = __hmul2(u0[1], u0[1]);
            __half2 d1a = __hmul2(u0[0], v1r[0]);
            __half2 d1b = __hmul2(u0[1], v1r[1]);
            s2a = __hfma2(u0[2], u0[2], s2a);  d1a = __hfma2(u0[2], v1r[2], d1a);
            s2b = __hfma2(u0[3], u0[3], s2b);  d1b = __hfma2(u0[3], v1r[3], d1b);
            s2a = __hfma2(u1[0], u1[0], s2a);  d1a = __hfma2(u1[0], v1r[4], d1a);
            s2b = __hfma2(u1[1], u1[1], s2b);  d1b = __hfma2(u1[1], v1r[5], d1b);
            s2a = __hfma2(u1[2], u1[2], s2a);  d1a = __hfma2(u1[2], v1r[6], d1a);
            s2b = __hfma2(u1[3], u1[3], s2b);  d1b = __hfma2(u1[3], v1r[7], d1b);
            __half2 s2h = __hadd2(s2a, s2b);
            __half2 d1h = __hadd2(d1a, d1b);
            float dot2 = 0.f;
            if (IT == 3) {
                __half2 d2a = __hmul2(u0[0], v2r[0]);
                __half2 d2b = __hmul2(u0[1], v2r[1]);
                d2a = __hfma2(u0[2], v2r[2], d2a);
                d2b = __hfma2(u0[3], v2r[3], d2b);
                d2a = __hfma2(u1[0], v2r[4], d2a);
                d2b = __hfma2(u1[1], v2r[5], d2b);
                d2a = __hfma2(u1[2], v2r[6], d2a);
                d2b = __hfma2(u1[3], v2r[7], d2b);
                __half2 d2h = __hadd2(d2a, d2b);
                dot2 = __low2float(d2h) + __high2float(d2h);
            }
            float s2   = __low2float(s2h) + __high2float(s2h);
            float dot1 = __low2float(d1h) + __high2float(d1h);
            float sc = sqrtf(s2) / (0.5f + s2);
            float usq = sc * sc * s2;
            float dd = 1.f - (usq - 2.f * sc * dot1 + vn1r);
            if (IT == 3) dd += 1.f - (usq - 2.f * sc * dot2 + vn2r);
            e[j] = __expf(dd);         // logits bounded -> safe without max-subtract
            e_sm[j][tid] = e[j];
        }
        __syncthreads();

        // block softmax denominators: warp w reduces row w
        {
            float4 t4 = *(const float4*)&e_sm[warp][lane * 4];
            float s = (t4.x + t4.y) + (t4.z + t4.w);
#pragma unroll
            for (int o = 16; o > 0; o >>= 1) s += __shfl_xor_sync(0xffffffffu, s, o);
            if (lane == 0) inv_sm[warp] = 1.f / s;
        }
        __syncthreads();

        // accumulate t, S from registers
        __half2 hq[8];
#pragma unroll
        for (int m = 0; m < 8; m++) hq[m] = __float2half2_rn(0.f);
#pragma unroll
        for (int j = 0; j < 4; j++) {
            float c = e[j] * inv_sm[j];
            __half2 c2 = __float2half2_rn(c);
            const __half2* u0 = (const __half2*)&ub[q & 1][j][0];
            const __half2* u1 = (const __half2*)&ub[q & 1][j][1];
            hq[0] = __hfma2(u0[0], c2, hq[0]);
            hq[1] = __hfma2(u0[1], c2, hq[1]);
            hq[2] = __hfma2(u0[2], c2, hq[2]);
            hq[3] = __hfma2(u0[3], c2, hq[3]);
            hq[4] = __hfma2(u1[0], c2, hq[4]);
            hq[5] = __hfma2(u1[1], c2, hq[5]);
            hq[6] = __hfma2(u1[2], c2, hq[6]);
            hq[7] = __hfma2(u1[3], c2, hq[7]);
            sacc += c;
        }
#pragma unroll
        for (int m = 0; m < 8; m++) {
            float2 f = __half22float2(hq[m]);
            tacc[2*m]   += f.x;
            tacc[2*m+1] += f.y;
        }
    }

    // flush: thread owns k fully across the chunk
    float* gt = g_t[IT - 1] + b * KD_ + tid * 16;
#pragma unroll
    for (int m = 0; m < 16; m++) atomicAdd(gt + m, tacc[m]);
    atomicAdd(&g_S[IT - 2][b * K_ + tid], sacc);
}

// ---------------- final ----------------
__global__ void k_final(float* __restrict__ out) {
    const int idx = blockIdx.x * 256 + threadIdx.x;
    const float inv = 1.0f / g_S[1][idx];
    const float4* tp = reinterpret_cast<const float4*>(&g_t[2][0] + idx * 16);
    float w[16]; float s2 = 0.f;
#pragma unroll
    for (int q = 0; q < 4; q++) {
        float4 tv = tp[q];
        w[q*4+0]=tv.x*inv; w[q*4+1]=tv.y*inv; w[q*4+2]=tv.z*inv; w[q*4+3]=tv.w*inv;
        s2 += w[q*4+0]*w[q*4+0] + w[q*4+1]*w[q*4+1] + w[q*4+2]*w[q*4+2] + w[q*4+3]*w[q*4+3];
    }
    float sc = sqrtf(s2) / (0.5f + s2);
    float4* op = reinterpret_cast<float4*>(out + idx * 16);
#pragma unroll
    for (int q = 0; q < 4; q++) {
        float4 o; o.x=sc*w[q*4+0]; o.y=sc*w[q*4+1]; o.z=sc*w[q*4+2]; o.w=sc*w[q*4+3];
        op[q] = o;
    }
    out[B_ * KD_ + idx] = s2 / (0.5f + s2);  // ||v||
}

// ---------------- launch ----------------
extern "C" void kernel_launch(void* const* d_in, const int* in_sizes, int n_in,
                              void* d_out, int out_size) {
    const float* x      = (const float*)d_in[0];
    const void*  labels = d_in[2];
    const float* W1     = (const float*)d_in[3];
    float*       out    = (float*)d_out;

    const int SMEMP = 32768 + 3 * 20480;   // 94208 (pass1)
    cudaFuncSetAttribute((const void*)k_pass1, cudaFuncAttributeMaxDynamicSharedMemorySize, SMEMP);

    k_init<<<768, 256>>>();
    k_pass1<<<dim3(128, 8), 256, SMEMP>>>(x, labels, W1);
    k_finalize<<<16, 256>>>(0);               // v0 = squash(sum_i u / 2048)
    k_route<2><<<2048, 128>>>();              // dd(v0) -> t1, S0
    k_finalize<<<16, 256>>>(1);               // v1 = squash(t1/S0)
    k_route<3><<<2048, 128>>>();              // dd(v0)+dd(v1) -> t2, S1
    k_final<<<16, 256>>>(out);                // poses + activations
    (void)in_sizes; (void)n_in; (void)out_size;
}

// round 14
// speedup vs baseline: 1.0733x; 1.0205x over previous
#include <cuda_runtime.h>
#include <cuda_fp16.h>
#include <cstdint>

#define B_  32
#define N_  2048
#define K_  128
#define CI_ 16
#define CO_ 16
#define KD_ (K_*CO_)   // 2048

typedef unsigned long long ull;

// XOR swizzle: permutes 16B cells within 1KB atoms -> conflict-free
#define SW(o) ((o) ^ (((o) >> 3) & 0x70))

// cp.async helpers
#define CP_ASYNC16(saddr, gptr) \
    asm volatile("cp.async.cg.shared.global [%0], [%1], 16;" :: "r"(saddr), "l"(gptr))
#define CP_COMMIT() asm volatile("cp.async.commit_group;")
#define CP_WAIT0()  asm volatile("cp.async.wait_group 0;" ::: "memory")
#define CP_WAIT1()  asm volatile("cp.async.wait_group 1;" ::: "memory")
#define CP_WAIT2()  asm volatile("cp.async.wait_group 2;" ::: "memory")

// ---------------- scratch (device globals; no allocation allowed) ----------------
__device__ __half g_uhat[(size_t)B_ * N_ * KD_];   // [b][i][k][d]  fp16, 268MB
__device__ float  g_t[3][B_ * KD_];
__device__ float  g_S[2][B_ * K_];
__device__ float  g_v[2][B_ * KD_];
__device__ float  g_vn[2][B_ * K_];

// ---------------- f32x2 packed helpers ----------------
__device__ __forceinline__ ull pack2(float a, float b) {
    ull r; asm("mov.b64 %0, {%1,%2};" : "=l"(r) : "f"(a), "f"(b)); return r;
}
__device__ __forceinline__ void unpack2(ull v, float& a, float& b) {
    asm("mov.b64 {%0,%1}, %2;" : "=f"(a), "=f"(b) : "l"(v));
}
__device__ __forceinline__ void ffma2(ull& d, ull a, ull b) {
    asm("fma.rn.f32x2 %0, %1, %2, %0;" : "+l"(d) : "l"(a), "l"(b));
}
__device__ __forceinline__ void fadd2(ull& d, ull a) {
    asm("add.rn.f32x2 %0, %0, %1;" : "+l"(d) : "l"(a));
}

// labels dtype-agnostic (int32 vs int64); labels = arange(128)
__device__ __forceinline__ int load_label(const void* labels, int k) {
    const int* p32 = (const int*)labels;
    if (p32[1] == 1) return p32[k];
    return (int)((const long long*)labels)[k];
}

// ---------------- init ----------------
__global__ void k_init() {
    int idx = blockIdx.x * 256 + threadIdx.x;
    if (idx < 3 * B_ * KD_) (&g_t[0][0])[idx] = 0.f;
    if (idx < 2 * B_ * K_)  (&g_S[0][0])[idx] = 0.f;
}

// ---------------- pass 1 (unchanged from R13) ----------------
__global__ void __launch_bounds__(256, 2) k_pass1(const float* __restrict__ x,
                                                  const void* __restrict__ labels,
                                                  const float* __restrict__ W1) {
    extern __shared__ __align__(16) char ps[];
    float* xs = (float*)ps;                 // 32KB
    char*  wb = ps + 32768;                 // 3 x 20480 (pitch-80 per-thread slots)
    const uint32_t wb_s = (uint32_t)__cvta_generic_to_shared(wb);

    const int tid = threadIdx.x;
    const int kd  = blockIdx.y * 256 + tid;
    const int k   = kd >> 4;
    const int d   = kd & 15;
    int ksrc = load_label(labels, k);
    if ((unsigned)ksrc >= (unsigned)K_) ksrc = k;
    const int i0  = blockIdx.x * 16;

    const char*  wrow  = (const char*)(W1 + (((size_t)i0 * K_ + ksrc) * CO_ + d) * CI_);
    const size_t wstep = (size_t)K_ * CO_ * CI_ * 4;

#pragma unroll
    for (int p = 0; p < 3; p++) {
        uint32_t dst = wb_s + p * 20480 + tid * 80;
        const char* s = wrow + (size_t)p * wstep;
        CP_ASYNC16(dst,      s);
        CP_ASYNC16(dst + 16, s + 16);
        CP_ASYNC16(dst + 32, s + 32);
        CP_ASYNC16(dst + 48, s + 48);
        CP_COMMIT();
    }

    for (int e = tid; e < 8192; e += 256) {
        const int b = e >> 8, rem = e & 255, i = rem >> 4, c = rem & 15;
        xs[i * 512 + ((b >> 1) * 16 + c) * 2 + (b & 1)] =
            x[((size_t)b * N_ + i0 + i) * CI_ + c];
    }
    __syncthreads();

    ull tsum[16];
#pragma unroll
    for (int bp = 0; bp < 16; bp++) tsum[bp] = 0ull;

    for (int ii = 0; ii < 16; ii++) {
        if (ii < 14) { CP_WAIT2(); } else if (ii == 14) { CP_WAIT1(); } else { CP_WAIT0(); }

        const float4* wt = (const float4*)(wb + (ii % 3) * 20480 + tid * 80);
        float4 cw0 = wt[0], cw1 = wt[1], cw2 = wt[2], cw3 = wt[3];
        ull wd[16];
        wd[0]=pack2(cw0.x,cw0.x); wd[1]=pack2(cw0.y,cw0.y); wd[2]=pack2(cw0.z,cw0.z); wd[3]=pack2(cw0.w,cw0.w);
        wd[4]=pack2(cw1.x,cw1.x); wd[5]=pack2(cw1.y,cw1.y); wd[6]=pack2(cw1.z,cw1.z); wd[7]=pack2(cw1.w,cw1.w);
        wd[8]=pack2(cw2.x,cw2.x); wd[9]=pack2(cw2.y,cw2.y); wd[10]=pack2(cw2.z,cw2.z); wd[11]=pack2(cw2.w,cw2.w);
        wd[12]=pack2(cw3.x,cw3.x); wd[13]=pack2(cw3.y,cw3.y); wd[14]=pack2(cw3.z,cw3.z); wd[15]=pack2(cw3.w,cw3.w);

        if (ii < 13) {
            uint32_t dst = wb_s + (ii % 3) * 20480 + tid * 80;
            const char* s = wrow + (size_t)(ii + 3) * wstep;
            CP_ASYNC16(dst,      s);
            CP_ASYNC16(dst + 16, s + 16);
            CP_ASYNC16(dst + 32, s + 32);
            CP_ASYNC16(dst + 48, s + 48);
            CP_COMMIT();
        }

        const int i = i0 + ii;
        __half* ubase = g_uhat + (size_t)i * KD_ + kd;
#pragma unroll
        for (int bp = 0; bp < 16; bp++) {
            const ulonglong2* xq = reinterpret_cast<const ulonglong2*>(xs + ii * 512 + bp * 32);
            ulonglong2 p0 = xq[0], p1 = xq[1], p2 = xq[2], p3 = xq[3];
            ulonglong2 p4 = xq[4], p5 = xq[5], p6 = xq[6], p7 = xq[7];
            ull acc0 = 0ull, acc1 = 0ull;
            ffma2(acc0, wd[0],  p0.x); ffma2(acc1, wd[1],  p0.y);
            ffma2(acc0, wd[2],  p1.x); ffma2(acc1, wd[3],  p1.y);
            ffma2(acc0, wd[4],  p2.x); ffma2(acc1, wd[5],  p2.y);
            ffma2(acc0, wd[6],  p3.x); ffma2(acc1, wd[7],  p3.y);
            ffma2(acc0, wd[8],  p4.x); ffma2(acc1, wd[9],  p4.y);
            ffma2(acc0, wd[10], p5.x); ffma2(acc1, wd[11], p5.y);
            ffma2(acc0, wd[12], p6.x); ffma2(acc1, wd[13], p6.y);
            ffma2(acc0, wd[14], p7.x); ffma2(acc1, wd[15], p7.y);
            fadd2(acc0, acc1);
            fadd2(tsum[bp], acc0);
            float lo, hi; unpack2(acc0, lo, hi);
            ubase[(size_t)(2 * bp)     * N_ * KD_] = __float2half_rn(lo);
            ubase[(size_t)(2 * bp + 1) * N_ * KD_] = __float2half_rn(hi);
        }
    }
#pragma unroll
    for (int bp = 0; bp < 16; bp++) {
        float a, bb; unpack2(tsum[bp], a, bb);
        atomicAdd(&g_t[0][(2 * bp)     * KD_ + kd], a);
        atomicAdd(&g_t[0][(2 * bp + 1) * KD_ + kd], bb);
    }
}

// ---------------- finalize ----------------
__global__ void k_finalize(int which) {
    const int idx = blockIdx.x * 256 + threadIdx.x;
    const float* t = g_t[which];
    float inv = (which == 0) ? (1.0f / 2048.0f) : (1.0f / g_S[0][idx]);
    const float4* tp = reinterpret_cast<const float4*>(t + idx * 16);
    float w[16]; float s2 = 0.f;
#pragma unroll
    for (int q = 0; q < 4; q++) {
        float4 tv = tp[q];
        w[q*4+0]=tv.x*inv; w[q*4+1]=tv.y*inv; w[q*4+2]=tv.z*inv; w[q*4+3]=tv.w*inv;
        s2 += w[q*4+0]*w[q*4+0] + w[q*4+1]*w[q*4+1] + w[q*4+2]*w[q*4+2] + w[q*4+3]*w[q*4+3];
    }
    float sc = sqrtf(s2) / (0.5f + s2);
    float4* vp = reinterpret_cast<float4*>(g_v[which] + idx * 16);
#pragma unroll
    for (int q = 0; q < 4; q++) {
        float4 o; o.x=sc*w[q*4+0]; o.y=sc*w[q*4+1]; o.z=sc*w[q*4+2]; o.w=sc*w[q*4+3];
        vp[q] = o;
    }
    g_vn[which][idx] = sc * sc * s2;
}

// ---------------- routing pass: thread-owns-k + per-thread cp.async ring --------
// grid 2048 (32 b * 64 chunks of 32 i); block 128. Thread tid owns k=tid; v/vn in
// registers. u[i][tid] staged via depth-3 ring of per-thread 32B SMEM slots —
// cp.async.wait_group alone orders producer/consumer (thread reads only its own
// slot), so the ring adds ZERO barriers. ~2 full 16KB groups in flight per CTA.
template <int IT>
__global__ void __launch_bounds__(128, 4) k_route() {
    extern __shared__ __align__(1024) char rbase[];
    char*  ring   = rbase;                       // 3 x 16KB (group = 4 i x 128 thr x 32B)
    float* e_sm   = (float*)(rbase + 49152);     // [4][128]
    float* inv_sm = (float*)(rbase + 51200);     // [4]

    const int tid = threadIdx.x, lane = tid & 31, warp = tid >> 5;
    const int b   = blockIdx.x >> 6;
    const int ch  = blockIdx.x & 63;
    const int i0  = ch * 32;

    const uint32_t ring_s = (uint32_t)__cvta_generic_to_shared(ring);
    const uint32_t sw0 = SW(tid * 32);
    const uint32_t sw1 = SW(tid * 32 + 16);

    // u row base for own k; i stride = 4096 bytes
    const char* ubase = (const char*)(g_uhat + ((size_t)b * N_ + i0) * KD_) + tid * 32;

    // prime groups 0,1,2 (one commit group per i-group)
#pragma unroll
    for (int g = 0; g < 3; g++) {
        uint32_t gb = ring_s + g * 16384;
#pragma unroll
        for (int j = 0; j < 4; j++) {
            const char* src = ubase + (size_t)(g * 4 + j) * 4096;
            CP_ASYNC16(gb + j * 4096 + sw0, src);
            CP_ASYNC16(gb + j * 4096 + sw1, src + 16);
        }
        CP_COMMIT();
    }

    // register-resident v, vn for own k = tid (overlaps the transfers)
    __half2 v1r[8], v2r[8];
    {
        const float* vs = g_v[0] + b * KD_ + tid * 16;
#pragma unroll
        for (int m = 0; m < 8; m++) v1r[m] = __floats2half2_rn(vs[2*m], vs[2*m+1]);
        if (IT == 3) {
            const float* ws = g_v[1] + b * KD_ + tid * 16;
#pragma unroll
            for (int m = 0; m < 8; m++) v2r[m] = __floats2half2_rn(ws[2*m], ws[2*m+1]);
        }
    }
    const float vn1r = g_vn[0][b * K_ + tid];
    const float vn2r = (IT == 3) ? g_vn[1][b * K_ + tid] : 0.f;

    float tacc[16];
#pragma unroll
    for (int m = 0; m < 16; m++) tacc[m] = 0.f;
    float sacc = 0.f;

#pragma unroll
    for (int q = 0; q < 8; q++) {
        if (q < 6) { CP_WAIT2(); } else if (q == 6) { CP_WAIT1(); } else { CP_WAIT0(); }

        const char* gb = ring + (q % 3) * 16384;

        // own-slot LDS + logits + exp (u kept in regs for the accumulate below)
        uint4 ur[4][2];
        float e[4];
#pragma unroll
        for (int j = 0; j < 4; j++) {
            ur[j][0] = *(const uint4*)(gb + j * 4096 + sw0);
            ur[j][1] = *(const uint4*)(gb + j * 4096 + sw1);
            const __half2* u0 = (const __half2*)&ur[j][0];
            const __half2* u1 = (const __half2*)&ur[j][1];
            __half2 s2a = __hmul2(u0[0], u0[0]);
            __half2 s2b = __hmul2(u0[1], u0[1]);
            __half2 d1a = __hmul2(u0[0], v1r[0]);
            __half2 d1b = __hmul2(u0[1], v1r[1]);
            s2a = __hfma2(u0[2], u0[2], s2a);  d1a = __hfma2(u0[2], v1r[2], d1a);
            s2b = __hfma2(u0[3], u0[3], s2b);  d1b = __hfma2(u0[3], v1r[3], d1b);
            s2a = __hfma2(u1[0], u1[0], s2a);  d1a = __hfma2(u1[0], v1r[4], d1a);
            s2b = __hfma2(u1[1], u1[1], s2b);  d1b = __hfma2(u1[1], v1r[5], d1b);
            s2a = __hfma2(u1[2], u1[2], s2a);  d1a = __hfma2(u1[2], v1r[6], d1a);
            s2b = __hfma2(u1[3], u1[3], s2b);  d1b = __hfma2(u1[3], v1r[7], d1b);
            __half2 s2h = __hadd2(s2a, s2b);
            __half2 d1h = __hadd2(d1a, d1b);
            float dot2 = 0.f;
            if (IT == 3) {
                __half2 d2a = __hmul2(u0[0], v2r[0]);
                __half2 d2b = __hmul2(u0[1], v2r[1]);
                d2a = __hfma2(u0[2], v2r[2], d2a);
                d2b = __hfma2(u0[3], v2r[3], d2b);
                d2a = __hfma2(u1[0], v2r[4], d2a);
                d2b = __hfma2(u1[1], v2r[5], d2b);
                d2a = __hfma2(u1[2], v2r[6], d2a);
                d2b = __hfma2(u1[3], v2r[7], d2b);
                __half2 d2h = __hadd2(d2a, d2b);
                dot2 = __low2float(d2h) + __high2float(d2h);
            }
            float s2   = __low2float(s2h) + __high2float(s2h);
            float dot1 = __low2float(d1h) + __high2float(d1h);
            float sc = sqrtf(s2) / (0.5f + s2);
            float usq = sc * sc * s2;
            float dd = 1.f - (usq - 2.f * sc * dot1 + vn1r);
            if (IT == 3) dd += 1.f - (usq - 2.f * sc * dot2 + vn2r);
            e[j] = __expf(dd);         // logits bounded -> safe without max-subtract
            e_sm[j * 128 + tid] = e[j];
        }
        __syncthreads();

        // block softmax denominators: warp w reduces row w
        {
            float4 t4 = *(const float4*)&e_sm[warp * 128 + lane * 4];
            float s = (t4.x + t4.y) + (t4.z + t4.w);
#pragma unroll
            for (int o = 16; o > 0; o >>= 1) s += __shfl_xor_sync(0xffffffffu, s, o);
            if (lane == 0) inv_sm[warp] = 1.f / s;
        }
        __syncthreads();

        // accumulate t, S from registers
        __half2 hq[8];
#pragma unroll
        for (int m = 0; m < 8; m++) hq[m] = __float2half2_rn(0.f);
#pragma unroll
        for (int j = 0; j < 4; j++) {
            float c = e[j] * inv_sm[j];
            __half2 c2 = __float2half2_rn(c);
            const __half2* u0 = (const __half2*)&ur[j][0];
            const __half2* u1 = (const __half2*)&ur[j][1];
            hq[0] = __hfma2(u0[0], c2, hq[0]);
            hq[1] = __hfma2(u0[1], c2, hq[1]);
            hq[2] = __hfma2(u0[2], c2, hq[2]);
            hq[3] = __hfma2(u0[3], c2, hq[3]);
            hq[4] = __hfma2(u1[0], c2, hq[4]);
            hq[5] = __hfma2(u1[1], c2, hq[5]);
            hq[6] = __hfma2(u1[2], c2, hq[6]);
            hq[7] = __hfma2(u1[3], c2, hq[7]);
            sacc += c;
        }
#pragma unroll
        for (int m = 0; m < 8; m++) {
            float2 f = __half22float2(hq[m]);
            tacc[2*m]   += f.x;
            tacc[2*m+1] += f.y;
        }

        // refill this ring slot for group q+3 (own data already in registers)
        if (q < 5) {
            uint32_t dst = ring_s + (q % 3) * 16384;
            const char* src = ubase + (size_t)(q + 3) * 4 * 4096;
#pragma unroll
            for (int j = 0; j < 4; j++) {
                CP_ASYNC16(dst + j * 4096 + sw0, src + (size_t)j * 4096);
                CP_ASYNC16(dst + j * 4096 + sw1, src + (size_t)j * 4096 + 16);
            }
            CP_COMMIT();
        }
    }

    // flush: thread owns k fully across the chunk
    float* gt = g_t[IT - 1] + b * KD_ + tid * 16;
#pragma unroll
    for (int m = 0; m < 16; m++) atomicAdd(gt + m, tacc[m]);
    atomicAdd(&g_S[IT - 2][b * K_ + tid], sacc);
}

// ---------------- final ----------------
__global__ void k_final(float* __restrict__ out) {
    const int idx = blockIdx.x * 256 + threadIdx.x;
    const float inv = 1.0f / g_S[1][idx];
    const float4* tp = reinterpret_cast<const float4*>(&g_t[2][0] + idx * 16);
    float w[16]; float s2 = 0.f;
#pragma unroll
    for (int q = 0; q < 4; q++) {
        float4 tv = tp[q];
        w[q*4+0]=tv.x*inv; w[q*4+1]=tv.y*inv; w[q*4+2]=tv.z*inv; w[q*4+3]=tv.w*inv;
        s2 += w[q*4+0]*w[q*4+0] + w[q*4+1]*w[q*4+1] + w[q*4+2]*w[q*4+2] + w[q*4+3]*w[q*4+3];
    }
    float sc = sqrtf(s2) / (0.5f + s2);
    float4* op = reinterpret_cast<float4*>(out + idx * 16);
#pragma unroll
    for (int q = 0; q < 4; q++) {
        float4 o; o.x=sc*w[q*4+0]; o.y=sc*w[q*4+1]; o.z=sc*w[q*4+2]; o.w=sc*w[q*4+3];
        op[q] = o;
    }
    out[B_ * KD_ + idx] = s2 / (0.5f + s2);  // ||v||
}

// ---------------- launch ----------------
extern "C" void kernel_launch(void* const* d_in, const int* in_sizes, int n_in,
                              void* d_out, int out_size) {
    const float* x      = (const float*)d_in[0];
    const void*  labels = d_in[2];
    const float* W1     = (const float*)d_in[3];
    float*       out    = (float*)d_out;

    const int SMEMP = 32768 + 3 * 20480;   // 94208 (pass1)
    const int SMEMR = 51264;               // route: ring 48K + e_sm 2K + inv
    cudaFuncSetAttribute((const void*)k_pass1,    cudaFuncAttributeMaxDynamicSharedMemorySize, SMEMP);
    cudaFuncSetAttribute((const void*)k_route<2>, cudaFuncAttributeMaxDynamicSharedMemorySize, SMEMR);
    cudaFuncSetAttribute((const void*)k_route<3>, cudaFuncAttributeMaxDynamicSharedMemorySize, SMEMR);

    k_init<<<768, 256>>>();
    k_pass1<<<dim3(128, 8), 256, SMEMP>>>(x, labels, W1);
    k_finalize<<<16, 256>>>(0);               // v0 = squash(sum_i u / 2048)
    k_route<2><<<2048, 128, SMEMR>>>();       // dd(v0) -> t1, S0
    k_finalize<<<16, 256>>>(1);               // v1 = squash(t1/S0)
    k_route<3><<<2048, 128, SMEMR>>>();       // dd(v0)+dd(v1) -> t2, S1
    k_final<<<16, 256>>>(out);                // poses + activations
    (void)in_sizes; (void)n_in; (void)out_size;
}